// round 4
// baseline (speedup 1.0000x reference)
#include <cuda_runtime.h>
#include <cuda_bf16.h>
#include <cstdint>
#include <cstddef>

#define BB 8
#define LL 2048
#define DD 1024

// ---------------- scratch (device globals; allocation-free) ----------------
__device__ float g_ks[BB * LL];
__device__ float g_e[BB * LL];
__device__ float g_zinv[BB * LL];
__device__ int g_is32;
__device__ unsigned char g_mask8[(size_t)BB * LL * LL];          // 0/1 bytes (for zattn)
__device__ __nv_bfloat16 g_mab[(size_t)BB * LL * LL];            // mask as bf16 0/1 (A of hi GEMM)
__device__ unsigned char g_ma8[(size_t)BB * LL * LL];            // mask as e4m3 0/1 (A of lo GEMM)
__device__ __nv_bfloat16 g_uth[(size_t)BB * DD * LL];            // U^T hi bf16: [b][d][s]
__device__ unsigned char g_utl8[(size_t)BB * DD * LL];           // U^T lo e4m3 (scaled 2^12): [b][d][s]

#define LO_SCALE 4096.0f
#define LO_INV (1.0f / 4096.0f)

// ---------------- helpers ----------------
static __device__ __forceinline__ uint32_t smem_u32(const void* p) {
    uint32_t a;
    asm("{ .reg .u64 t; cvta.to.shared.u64 t, %1; cvt.u32.u64 %0, t; }" : "=r"(a) : "l"(p));
    return a;
}

#define STS128V(a, r0, r1, r2, r3) \
    asm volatile("st.shared.v4.b32 [%0], {%1, %2, %3, %4};" :: "r"(a), "r"(r0), "r"(r1), "r"(r2), "r"(r3) : "memory")

static __device__ __forceinline__ void ldsm4(uint32_t* r, uint32_t addr) {
    asm volatile("ldmatrix.sync.aligned.m8n8.x4.shared.b16 {%0,%1,%2,%3}, [%4];"
                 : "=r"(r[0]), "=r"(r[1]), "=r"(r[2]), "=r"(r[3]) : "r"(addr));
}

static __device__ __forceinline__ void mma_bf16(float* c, const uint32_t* a, const uint32_t* b) {
    asm volatile(
        "mma.sync.aligned.m16n8k16.row.col.f32.bf16.bf16.f32 "
        "{%0,%1,%2,%3}, {%4,%5,%6,%7}, {%8,%9}, {%0,%1,%2,%3};"
        : "+f"(c[0]), "+f"(c[1]), "+f"(c[2]), "+f"(c[3])
        : "r"(a[0]), "r"(a[1]), "r"(a[2]), "r"(a[3]), "r"(b[0]), "r"(b[1]));
}

static __device__ __forceinline__ void mma_fp8(float* c, const uint32_t* a, const uint32_t* b) {
    asm volatile(
        "mma.sync.aligned.m16n8k32.row.col.f32.e4m3.e4m3.f32 "
        "{%0,%1,%2,%3}, {%4,%5,%6,%7}, {%8,%9}, {%0,%1,%2,%3};"
        : "+f"(c[0]), "+f"(c[1]), "+f"(c[2]), "+f"(c[3])
        : "r"(a[0]), "r"(a[1]), "r"(a[2]), "r"(a[3]), "r"(b[0]), "r"(b[1]));
}

static __device__ __forceinline__ unsigned char f2e4m3(float v) {
    unsigned short h;
    asm("cvt.rn.satfinite.e4m3x2.f32 %0, %1, %2;" : "=h"(h) : "f"(0.0f), "f"(v));
    return (unsigned char)(h & 0xFF);
}

// swizzled SMEM offset: tiles are 128 rows x 128B rows (8 x 16B chunks)
#define SA(row, chunk) ((uint32_t)((row) * 128 + ((((uint32_t)(chunk)) ^ ((uint32_t)(row) & 7u)) << 4)))

// ---------------- Pass 0a: detect mask dtype (int32 vs uint8) ----------------
__global__ void detect_kernel(const unsigned int* m) {
    __shared__ int s;
    if (threadIdx.x == 0) s = 0;
    __syncthreads();
    if (m[threadIdx.x] & 0xFFFFFF00u) atomicOr(&s, 1);
    __syncthreads();
    if (threadIdx.x == 0) g_is32 = s ? 0 : 1;
}

// ---------------- Pass 0b: repack mask to byte / bf16 / e4m3 ----------------
__global__ __launch_bounds__(256) void repack_kernel(const void* maskp) {
    size_t base = ((size_t)blockIdx.x * 256 + threadIdx.x) * 16;
    unsigned char ob[16];
    if (g_is32) {
        const uint4* mi = (const uint4*)((const int*)maskp + base);
#pragma unroll
        for (int j = 0; j < 4; j++) {
            uint4 w = mi[j];
            ob[j * 4 + 0] = w.x ? 1 : 0;
            ob[j * 4 + 1] = w.y ? 1 : 0;
            ob[j * 4 + 2] = w.z ? 1 : 0;
            ob[j * 4 + 3] = w.w ? 1 : 0;
        }
    } else {
        *(uint4*)ob = *(const uint4*)((const unsigned char*)maskp + base);
    }
    *(uint4*)(g_mask8 + base) = *(uint4*)ob;
    // bf16 0/1 (1.0 where NOT masked)
    uint32_t mb[8];
#pragma unroll
    for (int j = 0; j < 8; j++) {
        uint32_t lo = ob[2 * j] ? 0u : 0x3F80u;
        uint32_t hi = ob[2 * j + 1] ? 0u : 0x3F80u;
        mb[j] = lo | (hi << 16);
    }
    uint4* mbp = (uint4*)((unsigned char*)g_mab + base * 2);
    mbp[0] = make_uint4(mb[0], mb[1], mb[2], mb[3]);
    mbp[1] = make_uint4(mb[4], mb[5], mb[6], mb[7]);
    // e4m3 0/1 (0x38 = 1.0)
    unsigned char a8[16];
#pragma unroll
    for (int j = 0; j < 16; j++) a8[j] = ob[j] ? 0u : 0x38u;
    *(uint4*)(g_ma8 + base) = *(uint4*)a8;
}

// ---------------- Pass 1: k_s[b,s] = k . W2 + b2 ----------------
__global__ __launch_bounds__(256) void ks_kernel(const float* __restrict__ k,
                                                 const float* __restrict__ W2,
                                                 const float* __restrict__ b2) {
    int w = threadIdx.x >> 5, lane = threadIdx.x & 31;
    int r = blockIdx.x * 8 + w;
    const float4* kr = (const float4*)(k + (size_t)r * DD);
    const float4* w4 = (const float4*)W2;
    float s = 0.f;
#pragma unroll
    for (int i = 0; i < 8; i++) {
        float4 a = kr[lane + 32 * i];
        float4 b = w4[lane + 32 * i];
        s += a.x * b.x + a.y * b.y + a.z * b.z + a.w * b.w;
    }
#pragma unroll
    for (int o = 16; o; o >>= 1) s += __shfl_xor_sync(0xFFFFFFFFu, s, o);
    if (lane == 0) g_ks[r] = s + b2[0];
}

// ---------------- Pass 2: per-b max and e = exp(ks - max) ----------------
__global__ __launch_bounds__(256) void maxexp_kernel() {
    int b = blockIdx.x;
    __shared__ float red[256];
    float m = -1e30f;
    for (int i = threadIdx.x; i < LL; i += 256) m = fmaxf(m, g_ks[b * LL + i]);
    red[threadIdx.x] = m;
    __syncthreads();
    for (int s = 128; s; s >>= 1) {
        if (threadIdx.x < s) red[threadIdx.x] = fmaxf(red[threadIdx.x], red[threadIdx.x + s]);
        __syncthreads();
    }
    float M = red[0];
    for (int i = threadIdx.x; i < LL; i += 256) g_e[b * LL + i] = expf(g_ks[b * LL + i] - M);
}

// ---------------- Pass 3: U^T build (hi bf16 + lo e4m3*2^12), [b][d][s] ----------------
__global__ __launch_bounds__(256) void ut_kernel(const float* __restrict__ v) {
    __shared__ float tile[32][33];
    int b = blockIdx.z;
    int s0 = blockIdx.y * 32, d0 = blockIdx.x * 32;
    int r = threadIdx.x >> 5, c = threadIdx.x & 31;
#pragma unroll
    for (int i = 0; i < 4; i++) {
        int sl = r + i * 8;
        tile[sl][c] = g_e[b * LL + s0 + sl] * v[((size_t)b * LL + s0 + sl) * DD + d0 + c];
    }
    __syncthreads();
#pragma unroll
    for (int i = 0; i < 4; i++) {
        int dl = r + i * 8;
        float u = tile[c][dl];
        __nv_bfloat16 hi = __float2bfloat16(u);
        float lo = (u - __bfloat162float(hi)) * LO_SCALE;
        size_t off = ((size_t)b * DD + d0 + dl) * LL + s0 + c;
        g_uth[off] = hi;
        g_utl8[off] = f2e4m3(lo);
    }
}

// ---------------- Pass 4: Z[b,l], zinv, attn output ----------------
__global__ __launch_bounds__(256) void zattn_kernel(float* __restrict__ attn) {
    __shared__ __align__(16) float se[LL];
    int b = blockIdx.x >> 8;
    int l0 = (blockIdx.x & 255) * 8;
    for (int i = threadIdx.x; i < LL; i += 256) se[i] = g_e[b * LL + i];
    __syncthreads();
    int w = threadIdx.x >> 5, lane = threadIdx.x & 31;
    int l = l0 + w;
    const uint32_t* mrow = (const uint32_t*)(g_mask8 + ((size_t)b * LL + l) * LL);
    const float4* e4 = (const float4*)se;
    uint32_t mw[16];
    float z = 0.f;
#pragma unroll
    for (int i = 0; i < 16; i++) {
        uint32_t m = mrow[lane + 32 * i];
        mw[i] = m;
        float4 ev = e4[lane + 32 * i];
        if (!(m & 0x000000FFu)) z += ev.x;
        if (!(m & 0x0000FF00u)) z += ev.y;
        if (!(m & 0x00FF0000u)) z += ev.z;
        if (!(m & 0xFF000000u)) z += ev.w;
    }
#pragma unroll
    for (int o = 16; o; o >>= 1) z += __shfl_xor_sync(0xFFFFFFFFu, z, o);
    float zi = 1.f / z;
    if (lane == 0) g_zinv[b * LL + l] = zi;
    float4* arow = (float4*)(attn + ((size_t)b * LL + l) * LL);
#pragma unroll
    for (int i = 0; i < 16; i++) {
        uint32_t m = mw[i];
        float4 ev = e4[lane + 32 * i];
        float4 o4;
        o4.x = (m & 0x000000FFu) ? 0.f : ev.x * zi;
        o4.y = (m & 0x0000FF00u) ? 0.f : ev.y * zi;
        o4.z = (m & 0x00FF0000u) ? 0.f : ev.z * zi;
        o4.w = (m & 0xFF000000u) ? 0.f : ev.w * zi;
        arow[lane + 32 * i] = o4;
    }
}

// ---------------- Pass 5a: hi GEMM (bf16): out = (Mbf @ Uhi) * zinv ----------------
// CTA tile 128(l) x 128(d), K-chunk 64(s). 8 warps: warpM = wid&3, warpN = wid>>2.
#define HI_A 0u
#define HI_H 16384u

__global__ __launch_bounds__(256, 2) void gemm_hi_kernel(float* __restrict__ out) {
    __shared__ __align__(128) unsigned char smem[32768];
    uint32_t sb = smem_u32(smem);
    int tid = threadIdx.x, wid = tid >> 5, lane = tid & 31;
    int b = blockIdx.z, l0 = blockIdx.y * 128, d0 = blockIdx.x * 128;
    int warpM = wid & 3, warpN = wid >> 2;

    float acc[2][8][4];
#pragma unroll
    for (int i = 0; i < 2; i++)
#pragma unroll
        for (int j = 0; j < 8; j++)
#pragma unroll
            for (int q = 0; q < 4; q++) acc[i][j][q] = 0.f;

    int sub = lane >> 3, l7 = lane & 7;
    int rA0 = warpM * 32 + (sub & 1) * 8 + l7;
    int chA = (sub >> 1);
    int rB0 = warpN * 64 + (sub >> 1) * 8 + l7;
    int chB = (sub & 1);

    int srow = tid >> 1;
    int sc4 = (tid & 1) * 4;
    const __nv_bfloat16* map = g_mab + ((size_t)(b * LL + l0 + srow)) * LL + sc4 * 8;
    const __nv_bfloat16* uhp = g_uth + ((size_t)(b * DD + d0 + srow)) * LL + sc4 * 8;

    for (int kt = 0; kt < 32; ++kt) {
        int s0 = kt * 64;
#pragma unroll
        for (int j = 0; j < 4; j++) {
            uint4 mv = *(const uint4*)(map + s0 + j * 8);
            STS128V(sb + HI_A + SA(srow, sc4 + j), mv.x, mv.y, mv.z, mv.w);
            uint4 uh = *(const uint4*)(uhp + s0 + j * 8);
            STS128V(sb + HI_H + SA(srow, sc4 + j), uh.x, uh.y, uh.z, uh.w);
        }
        __syncthreads();
#pragma unroll
        for (int ki = 0; ki < 4; ki++) {
            uint32_t af[2][4];
#pragma unroll
            for (int mi = 0; mi < 2; mi++)
                ldsm4(af[mi], sb + HI_A + SA(rA0 + mi * 16, ki * 2 + chA));
#pragma unroll
            for (int p = 0; p < 4; p++) {
                uint32_t bf[4];
                ldsm4(bf, sb + HI_H + SA(rB0 + p * 16, ki * 2 + chB));
#pragma unroll
                for (int mi = 0; mi < 2; mi++) {
                    mma_bf16(acc[mi][2 * p], af[mi], bf);
                    mma_bf16(acc[mi][2 * p + 1], af[mi], bf + 2);
                }
            }
        }
        __syncthreads();
    }

    int g = lane >> 2, tg = lane & 3;
#pragma unroll
    for (int mi = 0; mi < 2; mi++) {
#pragma unroll
        for (int h = 0; h < 2; h++) {
            int row = warpM * 32 + mi * 16 + h * 8 + g;
            float zi = g_zinv[b * LL + l0 + row];
            float* orow = out + ((size_t)(b * LL + l0 + row)) * DD + d0 + warpN * 64;
#pragma unroll
            for (int ni = 0; ni < 8; ni++) {
                float2 val;
                val.x = acc[mi][ni][h * 2] * zi;
                val.y = acc[mi][ni][h * 2 + 1] * zi;
                *(float2*)(orow + ni * 8 + tg * 2) = val;
            }
        }
    }
}

// ---------------- Pass 5b: lo GEMM (e4m3): out += (M8 @ Ulo8) * zinv / 2^12 ----------------
// CTA tile 128(l) x 128(d), K-chunk 128(s). fp8 rows: 128 bytes = 8 chunks.
#define LO_A 0u
#define LO_L 16384u

__global__ __launch_bounds__(256, 2) void gemm_lo_kernel(float* __restrict__ out) {
    __shared__ __align__(128) unsigned char smem[32768];
    uint32_t sb = smem_u32(smem);
    int tid = threadIdx.x, wid = tid >> 5, lane = tid & 31;
    int b = blockIdx.z, l0 = blockIdx.y * 128, d0 = blockIdx.x * 128;
    int warpM = wid & 3, warpN = wid >> 2;

    float acc[2][8][4];
#pragma unroll
    for (int i = 0; i < 2; i++)
#pragma unroll
        for (int j = 0; j < 8; j++)
#pragma unroll
            for (int q = 0; q < 4; q++) acc[i][j][q] = 0.f;

    int sub = lane >> 3, l7 = lane & 7;
    int rA0 = warpM * 32 + (sub & 1) * 8 + l7;
    int chA = (sub >> 1);
    int rB0 = warpN * 64 + (sub >> 1) * 8 + l7;
    int chB = (sub & 1);

    int srow = tid >> 1;
    int sc4 = (tid & 1) * 4;
    const unsigned char* map = g_ma8 + ((size_t)(b * LL + l0 + srow)) * LL + sc4 * 16;
    const unsigned char* ulp = g_utl8 + ((size_t)(b * DD + d0 + srow)) * LL + sc4 * 16;

    for (int kt = 0; kt < 16; ++kt) {
        int s0 = kt * 128;
#pragma unroll
        for (int j = 0; j < 4; j++) {
            uint4 mv = *(const uint4*)(map + s0 + j * 16);
            STS128V(sb + LO_A + SA(srow, sc4 + j), mv.x, mv.y, mv.z, mv.w);
            uint4 uv = *(const uint4*)(ulp + s0 + j * 16);
            STS128V(sb + LO_L + SA(srow, sc4 + j), uv.x, uv.y, uv.z, uv.w);
        }
        __syncthreads();
#pragma unroll
        for (int ki = 0; ki < 4; ki++) {
            uint32_t af[2][4];
#pragma unroll
            for (int mi = 0; mi < 2; mi++)
                ldsm4(af[mi], sb + LO_A + SA(rA0 + mi * 16, ki * 2 + chA));
#pragma unroll
            for (int p = 0; p < 4; p++) {
                uint32_t bf[4];
                ldsm4(bf, sb + LO_L + SA(rB0 + p * 16, ki * 2 + chB));
#pragma unroll
                for (int mi = 0; mi < 2; mi++) {
                    mma_fp8(acc[mi][2 * p], af[mi], bf);
                    mma_fp8(acc[mi][2 * p + 1], af[mi], bf + 2);
                }
            }
        }
        __syncthreads();
    }

    int g = lane >> 2, tg = lane & 3;
#pragma unroll
    for (int mi = 0; mi < 2; mi++) {
#pragma unroll
        for (int h = 0; h < 2; h++) {
            int row = warpM * 32 + mi * 16 + h * 8 + g;
            float c = g_zinv[b * LL + l0 + row] * LO_INV;
            float* orow = out + ((size_t)(b * LL + l0 + row)) * DD + d0 + warpN * 64;
#pragma unroll
            for (int ni = 0; ni < 8; ni++) {
                float2 cur = *(float2*)(orow + ni * 8 + tg * 2);
                cur.x += acc[mi][ni][h * 2] * c;
                cur.y += acc[mi][ni][h * 2 + 1] * c;
                *(float2*)(orow + ni * 8 + tg * 2) = cur;
            }
        }
    }
}

// ---------------- launch ----------------
extern "C" void kernel_launch(void* const* d_in, const int* in_sizes, int n_in,
                              void* d_out, int out_size) {
    (void)in_sizes; (void)n_in; (void)out_size;
    // inputs: 0=q, 1=k, 2=v, 3=attn_mask, 4=W1, 5=b1, 6=W2, 7=b2
    const float* k = (const float*)d_in[1];
    const float* v = (const float*)d_in[2];
    const void* mask = d_in[3];
    const float* W2 = (const float*)d_in[6];
    const float* b2 = (const float*)d_in[7];

    float* out = (float*)d_out;                // [B, L, D]
    float* attn = out + (size_t)BB * LL * DD;  // [B, L, L]

    detect_kernel<<<1, 1024>>>((const unsigned int*)mask);
    repack_kernel<<<(int)(((size_t)BB * LL * LL) / 4096), 256>>>(mask);
    ks_kernel<<<BB * LL / 8, 256>>>(k, W2, b2);
    maxexp_kernel<<<BB, 256>>>();
    ut_kernel<<<dim3(DD / 32, LL / 32, BB), 256>>>(v);
    zattn_kernel<<<BB * LL / 8, 256>>>(attn);
    gemm_hi_kernel<<<dim3(DD / 128, LL / 128, BB), 256>>>(out);
    gemm_lo_kernel<<<dim3(DD / 128, LL / 128, BB), 256>>>(out);
}

// round 5
// speedup vs baseline: 1.6434x; 1.6434x over previous
#include <cuda_runtime.h>
#include <cuda_bf16.h>
#include <cuda_fp16.h>
#include <cstdint>
#include <cstddef>

#define BB 8
#define LL 2048
#define DD 1024

// ---------------- scratch (device globals; allocation-free) ----------------
__device__ float g_ks[BB * LL];
__device__ float g_e[BB * LL];
__device__ float g_zinv[BB * LL];
__device__ int g_is32;
__device__ unsigned char g_mask8[(size_t)BB * LL * LL];  // 0/1 bytes
__device__ __half g_ut[(size_t)BB * DD * LL];            // U^T fp16: [b][d][s]

// ---------------- helpers ----------------
static __device__ __forceinline__ uint32_t smem_u32(const void* p) {
    uint32_t a;
    asm("{ .reg .u64 t; cvta.to.shared.u64 t, %1; cvt.u32.u64 %0, t; }" : "=r"(a) : "l"(p));
    return a;
}

#define STS128V(a, r0, r1, r2, r3) \
    asm volatile("st.shared.v4.b32 [%0], {%1, %2, %3, %4};" :: "r"(a), "r"(r0), "r"(r1), "r"(r2), "r"(r3) : "memory")

static __device__ __forceinline__ void ldsm4(uint32_t* r, uint32_t addr) {
    asm volatile("ldmatrix.sync.aligned.m8n8.x4.shared.b16 {%0,%1,%2,%3}, [%4];"
                 : "=r"(r[0]), "=r"(r[1]), "=r"(r[2]), "=r"(r[3]) : "r"(addr));
}

static __device__ __forceinline__ void mma_f16(float* c, const uint32_t* a, const uint32_t* b) {
    asm volatile(
        "mma.sync.aligned.m16n8k16.row.col.f32.f16.f16.f32 "
        "{%0,%1,%2,%3}, {%4,%5,%6,%7}, {%8,%9}, {%0,%1,%2,%3};"
        : "+f"(c[0]), "+f"(c[1]), "+f"(c[2]), "+f"(c[3])
        : "r"(a[0]), "r"(a[1]), "r"(a[2]), "r"(a[3]), "r"(b[0]), "r"(b[1]));
}

// swizzled SMEM offset: tiles are 128 rows x 64 fp16 (128B rows, 8 x 16B chunks)
#define SA(row, chunk) ((uint32_t)((row) * 128 + ((((uint32_t)(chunk)) ^ ((uint32_t)(row) & 7u)) << 4)))

// 2 mask bytes -> fp16x2 (1.0 where NOT masked, 0.0 where masked)
static __device__ __forceinline__ uint32_t m2f16(uint32_t w) {
    uint32_t lo = (w & 0x000000FFu) ? 0u : 0x3C00u;
    uint32_t hi = (w & 0x0000FF00u) ? 0u : 0x3C00u;
    return lo | (hi << 16);
}

// ---------------- Pass 0a: detect mask dtype (int32 vs uint8) ----------------
__global__ void detect_kernel(const unsigned int* m) {
    __shared__ int s;
    if (threadIdx.x == 0) s = 0;
    __syncthreads();
    if (m[threadIdx.x] & 0xFFFFFF00u) atomicOr(&s, 1);
    __syncthreads();
    if (threadIdx.x == 0) g_is32 = s ? 0 : 1;
}

// ---------------- Pass 0b: repack mask to normalized bytes ----------------
__global__ __launch_bounds__(256) void repack_kernel(const void* maskp) {
    size_t base = ((size_t)blockIdx.x * 256 + threadIdx.x) * 16;
    uint4 ov;
    if (g_is32) {
        const uint4* mi = (const uint4*)((const int*)maskp + base);
        unsigned char ob[16];
#pragma unroll
        for (int j = 0; j < 4; j++) {
            uint4 w = mi[j];
            ob[j * 4 + 0] = w.x ? 1 : 0;
            ob[j * 4 + 1] = w.y ? 1 : 0;
            ob[j * 4 + 2] = w.z ? 1 : 0;
            ob[j * 4 + 3] = w.w ? 1 : 0;
        }
        ov = *(const uint4*)ob;
    } else {
        ov = *(const uint4*)((const unsigned char*)maskp + base);
    }
    *(uint4*)(g_mask8 + base) = ov;
}

// ---------------- Pass 1: k_s[b,s] = k . W2 + b2 ----------------
__global__ __launch_bounds__(256) void ks_kernel(const float* __restrict__ k,
                                                 const float* __restrict__ W2,
                                                 const float* __restrict__ b2) {
    int w = threadIdx.x >> 5, lane = threadIdx.x & 31;
    int r = blockIdx.x * 8 + w;
    const float4* kr = (const float4*)(k + (size_t)r * DD);
    const float4* w4 = (const float4*)W2;
    float s = 0.f;
#pragma unroll
    for (int i = 0; i < 8; i++) {
        float4 a = kr[lane + 32 * i];
        float4 b = w4[lane + 32 * i];
        s += a.x * b.x + a.y * b.y + a.z * b.z + a.w * b.w;
    }
#pragma unroll
    for (int o = 16; o; o >>= 1) s += __shfl_xor_sync(0xFFFFFFFFu, s, o);
    if (lane == 0) g_ks[r] = s + b2[0];
}

// ---------------- Pass 2: per-b max and e = exp(ks - max) ----------------
__global__ __launch_bounds__(256) void maxexp_kernel() {
    int b = blockIdx.x;
    __shared__ float red[256];
    float m = -1e30f;
    for (int i = threadIdx.x; i < LL; i += 256) m = fmaxf(m, g_ks[b * LL + i]);
    red[threadIdx.x] = m;
    __syncthreads();
    for (int s = 128; s; s >>= 1) {
        if (threadIdx.x < s) red[threadIdx.x] = fmaxf(red[threadIdx.x], red[threadIdx.x + s]);
        __syncthreads();
    }
    float M = red[0];
    for (int i = threadIdx.x; i < LL; i += 256) g_e[b * LL + i] = expf(g_ks[b * LL + i] - M);
}

// ---------------- Pass 3: U^T fp16 build (U = e * v, transposed to [b][d][s]) ----------------
__global__ __launch_bounds__(256) void ut_kernel(const float* __restrict__ v) {
    __shared__ float tile[32][33];
    int b = blockIdx.z;
    int s0 = blockIdx.y * 32, d0 = blockIdx.x * 32;
    int r = threadIdx.x >> 5, c = threadIdx.x & 31;
#pragma unroll
    for (int i = 0; i < 4; i++) {
        int sl = r + i * 8;
        tile[sl][c] = g_e[b * LL + s0 + sl] * v[((size_t)b * LL + s0 + sl) * DD + d0 + c];
    }
    __syncthreads();
#pragma unroll
    for (int i = 0; i < 4; i++) {
        int dl = r + i * 8;
        float u = tile[c][dl];
        g_ut[((size_t)b * DD + d0 + dl) * LL + s0 + c] = __float2half(u);
    }
}

// ---------------- Pass 4: Z[b,l], zinv, attn output ----------------
__global__ __launch_bounds__(256) void zattn_kernel(float* __restrict__ attn) {
    __shared__ __align__(16) float se[LL];
    int b = blockIdx.x >> 8;
    int l0 = (blockIdx.x & 255) * 8;
    for (int i = threadIdx.x; i < LL; i += 256) se[i] = g_e[b * LL + i];
    __syncthreads();
    int w = threadIdx.x >> 5, lane = threadIdx.x & 31;
    int l = l0 + w;
    const uint32_t* mrow = (const uint32_t*)(g_mask8 + ((size_t)b * LL + l) * LL);
    const float4* e4 = (const float4*)se;
    uint32_t mw[16];
    float z = 0.f;
#pragma unroll
    for (int i = 0; i < 16; i++) {
        uint32_t m = mrow[lane + 32 * i];
        mw[i] = m;
        float4 ev = e4[lane + 32 * i];
        if (!(m & 0x000000FFu)) z += ev.x;
        if (!(m & 0x0000FF00u)) z += ev.y;
        if (!(m & 0x00FF0000u)) z += ev.z;
        if (!(m & 0xFF000000u)) z += ev.w;
    }
#pragma unroll
    for (int o = 16; o; o >>= 1) z += __shfl_xor_sync(0xFFFFFFFFu, z, o);
    float zi = 1.f / z;
    if (lane == 0) g_zinv[b * LL + l] = zi;
    float4* arow = (float4*)(attn + ((size_t)b * LL + l) * LL);
#pragma unroll
    for (int i = 0; i < 16; i++) {
        uint32_t m = mw[i];
        float4 ev = e4[lane + 32 * i];
        float4 o4;
        o4.x = (m & 0x000000FFu) ? 0.f : ev.x * zi;
        o4.y = (m & 0x0000FF00u) ? 0.f : ev.y * zi;
        o4.z = (m & 0x00FF0000u) ? 0.f : ev.z * zi;
        o4.w = (m & 0xFF000000u) ? 0.f : ev.w * zi;
        arow[lane + 32 * i] = o4;
    }
}

// ---------------- Pass 5: fp16 GEMM out = (M @ U) * zinv ----------------
// CTA tile: 128(l) x 128(d), K-chunk 64(s). 8 warps: warpM = wid&3 (32 rows),
// warpN = wid>>2 (64 cols). Warp does 2(M16) x 8(N8) mma tiles.
#define SMB_A 0u
#define SMB_U 16384u

__global__ __launch_bounds__(256, 2) void gemm_kernel(float* __restrict__ out) {
    __shared__ __align__(128) unsigned char smem[32768];
    uint32_t sb = smem_u32(smem);
    int tid = threadIdx.x, wid = tid >> 5, lane = tid & 31;
    int b = blockIdx.z, l0 = blockIdx.y * 128, d0 = blockIdx.x * 128;
    int warpM = wid & 3, warpN = wid >> 2;

    float acc[2][8][4];
#pragma unroll
    for (int i = 0; i < 2; i++)
#pragma unroll
        for (int j = 0; j < 8; j++)
#pragma unroll
            for (int q = 0; q < 4; q++) acc[i][j][q] = 0.f;

    int sub = lane >> 3, l7 = lane & 7;
    int rA0 = warpM * 32 + (sub & 1) * 8 + l7;   // + mi*16
    int chA = (sub >> 1);                         // + ki*2
    int rB0 = warpN * 64 + (sub >> 1) * 8 + l7;  // + p*16
    int chB = (sub & 1);                          // + ki*2

    // staging: thread handles row = tid>>1, chunks (tid&1)*4 .. +3
    int srow = tid >> 1;
    int sc4 = (tid & 1) * 4;
    const unsigned char* mrowp = g_mask8 + ((size_t)(b * LL + l0 + srow)) * LL + sc4 * 8;
    const __half* up = g_ut + ((size_t)(b * DD + d0 + srow)) * LL + sc4 * 8;

    for (int kt = 0; kt < 32; ++kt) {
        int s0 = kt * 64;
        // stage A (mask bytes -> fp16 0/1)
#pragma unroll
        for (int j = 0; j < 4; j++) {
            uint2 mv = *(const uint2*)(mrowp + s0 + j * 8);
            uint32_t r0 = m2f16(mv.x), r1 = m2f16(mv.x >> 16);
            uint32_t r2 = m2f16(mv.y), r3 = m2f16(mv.y >> 16);
            STS128V(sb + SMB_A + SA(srow, sc4 + j), r0, r1, r2, r3);
        }
        // stage B (U^T fp16)
#pragma unroll
        for (int j = 0; j < 4; j++) {
            uint4 uv = *(const uint4*)(up + s0 + j * 8);
            STS128V(sb + SMB_U + SA(srow, sc4 + j), uv.x, uv.y, uv.z, uv.w);
        }
        __syncthreads();

#pragma unroll
        for (int ki = 0; ki < 4; ki++) {
            uint32_t af[2][4];
#pragma unroll
            for (int mi = 0; mi < 2; mi++)
                ldsm4(af[mi], sb + SMB_A + SA(rA0 + mi * 16, ki * 2 + chA));
#pragma unroll
            for (int p = 0; p < 4; p++) {
                uint32_t bf[4];
                ldsm4(bf, sb + SMB_U + SA(rB0 + p * 16, ki * 2 + chB));
#pragma unroll
                for (int mi = 0; mi < 2; mi++) {
                    mma_f16(acc[mi][2 * p], af[mi], bf);
                    mma_f16(acc[mi][2 * p + 1], af[mi], bf + 2);
                }
            }
        }
        __syncthreads();
    }

    // epilogue: scale rows by zinv, store fp32
    int g = lane >> 2, tg = lane & 3;
#pragma unroll
    for (int mi = 0; mi < 2; mi++) {
#pragma unroll
        for (int h = 0; h < 2; h++) {
            int row = warpM * 32 + mi * 16 + h * 8 + g;
            float zi = g_zinv[b * LL + l0 + row];
            float* orow = out + ((size_t)(b * LL + l0 + row)) * DD + d0 + warpN * 64;
#pragma unroll
            for (int ni = 0; ni < 8; ni++) {
                float2 val;
                val.x = acc[mi][ni][h * 2] * zi;
                val.y = acc[mi][ni][h * 2 + 1] * zi;
                *(float2*)(orow + ni * 8 + tg * 2) = val;
            }
        }
    }
}

// ---------------- launch ----------------
extern "C" void kernel_launch(void* const* d_in, const int* in_sizes, int n_in,
                              void* d_out, int out_size) {
    (void)in_sizes; (void)n_in; (void)out_size;
    // inputs: 0=q, 1=k, 2=v, 3=attn_mask, 4=W1, 5=b1, 6=W2, 7=b2
    const float* k = (const float*)d_in[1];
    const float* v = (const float*)d_in[2];
    const void* mask = d_in[3];
    const float* W2 = (const float*)d_in[6];
    const float* b2 = (const float*)d_in[7];

    float* out = (float*)d_out;                // [B, L, D]
    float* attn = out + (size_t)BB * LL * DD;  // [B, L, L]

    detect_kernel<<<1, 1024>>>((const unsigned int*)mask);
    repack_kernel<<<(int)(((size_t)BB * LL * LL) / 4096), 256>>>(mask);
    ks_kernel<<<BB * LL / 8, 256>>>(k, W2, b2);
    maxexp_kernel<<<BB, 256>>>();
    ut_kernel<<<dim3(DD / 32, LL / 32, BB), 256>>>(v);
    zattn_kernel<<<BB * LL / 8, 256>>>(attn);
    gemm_kernel<<<dim3(DD / 128, LL / 128, BB), 256>>>(out);
}

// round 6
// speedup vs baseline: 1.9875x; 1.2094x over previous
#include <cuda_runtime.h>
#include <cuda_bf16.h>
#include <cuda_fp16.h>
#include <cstdint>
#include <cstddef>

#define BB 8
#define LL 2048
#define DD 1024

// ---------------- scratch (device globals; allocation-free) ----------------
__device__ float g_ks[BB * LL];
__device__ float g_e[BB * LL];
__device__ float g_zinv[BB * LL];
__device__ int g_is32;
__device__ unsigned char g_mask8[(size_t)BB * LL * LL];  // 0/1 bytes
__device__ __half g_ut[(size_t)BB * DD * LL];            // U^T fp16: [b][d][s]

// ---------------- helpers ----------------
static __device__ __forceinline__ uint32_t smem_u32(const void* p) {
    uint32_t a;
    asm("{ .reg .u64 t; cvta.to.shared.u64 t, %1; cvt.u32.u64 %0, t; }" : "=r"(a) : "l"(p));
    return a;
}

#define STS128V(a, r0, r1, r2, r3) \
    asm volatile("st.shared.v4.b32 [%0], {%1, %2, %3, %4};" :: "r"(a), "r"(r0), "r"(r1), "r"(r2), "r"(r3) : "memory")

#define CPASYNC16(dst, src) \
    asm volatile("cp.async.cg.shared.global [%0], [%1], 16;" :: "r"(dst), "l"(src) : "memory")
#define CPCOMMIT() asm volatile("cp.async.commit_group;" ::: "memory")
#define CPWAIT1() asm volatile("cp.async.wait_group 1;" ::: "memory")

static __device__ __forceinline__ void ldsm4(uint32_t* r, uint32_t addr) {
    asm volatile("ldmatrix.sync.aligned.m8n8.x4.shared.b16 {%0,%1,%2,%3}, [%4];"
                 : "=r"(r[0]), "=r"(r[1]), "=r"(r[2]), "=r"(r[3]) : "r"(addr));
}

static __device__ __forceinline__ void mma_f16(float* c, const uint32_t* a, const uint32_t* b) {
    asm volatile(
        "mma.sync.aligned.m16n8k16.row.col.f32.f16.f16.f32 "
        "{%0,%1,%2,%3}, {%4,%5,%6,%7}, {%8,%9}, {%0,%1,%2,%3};"
        : "+f"(c[0]), "+f"(c[1]), "+f"(c[2]), "+f"(c[3])
        : "r"(a[0]), "r"(a[1]), "r"(a[2]), "r"(a[3]), "r"(b[0]), "r"(b[1]));
}

// swizzled SMEM offset: tiles are 128 rows x 64 fp16 (128B rows, 8 x 16B chunks)
#define SA(row, chunk) ((uint32_t)((row) * 128 + ((((uint32_t)(chunk)) ^ ((uint32_t)(row) & 7u)) << 4)))

// 2 mask bytes -> fp16x2 (1.0 where NOT masked, 0.0 where masked)
static __device__ __forceinline__ uint32_t m2f16(uint32_t w) {
    uint32_t lo = (w & 0x000000FFu) ? 0u : 0x3C00u;
    uint32_t hi = (w & 0x0000FF00u) ? 0u : 0x3C00u;
    return lo | (hi << 16);
}

// ---------------- Pass 0a: detect mask dtype (int32 vs uint8) ----------------
__global__ void detect_kernel(const unsigned int* m) {
    __shared__ int s;
    if (threadIdx.x == 0) s = 0;
    __syncthreads();
    if (m[threadIdx.x] & 0xFFFFFF00u) atomicOr(&s, 1);
    __syncthreads();
    if (threadIdx.x == 0) g_is32 = s ? 0 : 1;
}

// ---------------- Pass 0b: repack mask to normalized bytes ----------------
__global__ __launch_bounds__(256) void repack_kernel(const void* maskp) {
    size_t base = ((size_t)blockIdx.x * 256 + threadIdx.x) * 16;
    uint4 ov;
    if (g_is32) {
        const uint4* mi = (const uint4*)((const int*)maskp + base);
        unsigned char ob[16];
#pragma unroll
        for (int j = 0; j < 4; j++) {
            uint4 w = mi[j];
            ob[j * 4 + 0] = w.x ? 1 : 0;
            ob[j * 4 + 1] = w.y ? 1 : 0;
            ob[j * 4 + 2] = w.z ? 1 : 0;
            ob[j * 4 + 3] = w.w ? 1 : 0;
        }
        ov = *(const uint4*)ob;
    } else {
        ov = *(const uint4*)((const unsigned char*)maskp + base);
    }
    *(uint4*)(g_mask8 + base) = ov;
}

// ---------------- Pass 1: k_s[b,s] = k . W2 + b2 ----------------
__global__ __launch_bounds__(256) void ks_kernel(const float* __restrict__ k,
                                                 const float* __restrict__ W2,
                                                 const float* __restrict__ b2) {
    int w = threadIdx.x >> 5, lane = threadIdx.x & 31;
    int r = blockIdx.x * 8 + w;
    const float4* kr = (const float4*)(k + (size_t)r * DD);
    const float4* w4 = (const float4*)W2;
    float s = 0.f;
#pragma unroll
    for (int i = 0; i < 8; i++) {
        float4 a = kr[lane + 32 * i];
        float4 b = w4[lane + 32 * i];
        s += a.x * b.x + a.y * b.y + a.z * b.z + a.w * b.w;
    }
#pragma unroll
    for (int o = 16; o; o >>= 1) s += __shfl_xor_sync(0xFFFFFFFFu, s, o);
    if (lane == 0) g_ks[r] = s + b2[0];
}

// ---------------- Pass 2: per-b max and e = exp(ks - max) ----------------
__global__ __launch_bounds__(256) void maxexp_kernel() {
    int b = blockIdx.x;
    __shared__ float red[256];
    float m = -1e30f;
    for (int i = threadIdx.x; i < LL; i += 256) m = fmaxf(m, g_ks[b * LL + i]);
    red[threadIdx.x] = m;
    __syncthreads();
    for (int s = 128; s; s >>= 1) {
        if (threadIdx.x < s) red[threadIdx.x] = fmaxf(red[threadIdx.x], red[threadIdx.x + s]);
        __syncthreads();
    }
    float M = red[0];
    for (int i = threadIdx.x; i < LL; i += 256) g_e[b * LL + i] = expf(g_ks[b * LL + i] - M);
}

// ---------------- Pass 3: U^T fp16 build (U = e * v, transposed to [b][d][s]) ----------------
__global__ __launch_bounds__(256) void ut_kernel(const float* __restrict__ v) {
    __shared__ float tile[32][33];
    int b = blockIdx.z;
    int s0 = blockIdx.y * 32, d0 = blockIdx.x * 32;
    int r = threadIdx.x >> 5, c = threadIdx.x & 31;
#pragma unroll
    for (int i = 0; i < 4; i++) {
        int sl = r + i * 8;
        tile[sl][c] = g_e[b * LL + s0 + sl] * v[((size_t)b * LL + s0 + sl) * DD + d0 + c];
    }
    __syncthreads();
#pragma unroll
    for (int i = 0; i < 4; i++) {
        int dl = r + i * 8;
        float u = tile[c][dl];
        g_ut[((size_t)b * DD + d0 + dl) * LL + s0 + c] = __float2half(u);
    }
}

// ---------------- Pass 4: Z[b,l], zinv, attn output ----------------
__global__ __launch_bounds__(256) void zattn_kernel(float* __restrict__ attn) {
    __shared__ __align__(16) float se[LL];
    int b = blockIdx.x >> 8;
    int l0 = (blockIdx.x & 255) * 8;
    for (int i = threadIdx.x; i < LL; i += 256) se[i] = g_e[b * LL + i];
    __syncthreads();
    int w = threadIdx.x >> 5, lane = threadIdx.x & 31;
    int l = l0 + w;
    const uint32_t* mrow = (const uint32_t*)(g_mask8 + ((size_t)b * LL + l) * LL);
    const float4* e4 = (const float4*)se;
    uint32_t mw[16];
    float z = 0.f;
#pragma unroll
    for (int i = 0; i < 16; i++) {
        uint32_t m = mrow[lane + 32 * i];
        mw[i] = m;
        float4 ev = e4[lane + 32 * i];
        if (!(m & 0x000000FFu)) z += ev.x;
        if (!(m & 0x0000FF00u)) z += ev.y;
        if (!(m & 0x00FF0000u)) z += ev.z;
        if (!(m & 0xFF000000u)) z += ev.w;
    }
#pragma unroll
    for (int o = 16; o; o >>= 1) z += __shfl_xor_sync(0xFFFFFFFFu, z, o);
    float zi = 1.f / z;
    if (lane == 0) g_zinv[b * LL + l] = zi;
    float4* arow = (float4*)(attn + ((size_t)b * LL + l) * LL);
#pragma unroll
    for (int i = 0; i < 16; i++) {
        uint32_t m = mw[i];
        float4 ev = e4[lane + 32 * i];
        float4 o4;
        o4.x = (m & 0x000000FFu) ? 0.f : ev.x * zi;
        o4.y = (m & 0x0000FF00u) ? 0.f : ev.y * zi;
        o4.z = (m & 0x00FF0000u) ? 0.f : ev.z * zi;
        o4.w = (m & 0xFF000000u) ? 0.f : ev.w * zi;
        arow[lane + 32 * i] = o4;
    }
}

// ---------------- Pass 5: fp16 GEMM out = (M @ U) * zinv, pipelined ----------------
// CTA tile: 128(l) x 128(d), K-chunk 64(s). 8 warps: warpM = wid&3, warpN = wid>>2.
// SMEM 48KB: A single buffer 16KB (register-pipelined) + B double buffer 2x16KB (cp.async).
#define SMB_A  0u
#define SMB_B0 16384u

__global__ __launch_bounds__(256, 2) void gemm_kernel(float* __restrict__ out) {
    __shared__ __align__(128) unsigned char smem[49152];
    uint32_t sb = smem_u32(smem);
    int tid = threadIdx.x, wid = tid >> 5, lane = tid & 31;
    int b = blockIdx.z, l0 = blockIdx.y * 128, d0 = blockIdx.x * 128;
    int warpM = wid & 3, warpN = wid >> 2;

    float acc[2][8][4];
#pragma unroll
    for (int i = 0; i < 2; i++)
#pragma unroll
        for (int j = 0; j < 8; j++)
#pragma unroll
            for (int q = 0; q < 4; q++) acc[i][j][q] = 0.f;

    int sub = lane >> 3, l7 = lane & 7;
    int rA0 = warpM * 32 + (sub & 1) * 8 + l7;   // + mi*16
    int chA = (sub >> 1);                         // + ki*2
    int rB0 = warpN * 64 + (sub >> 1) * 8 + l7;  // + p*16
    int chB = (sub & 1);                          // + ki*2

    // staging: thread handles row = tid>>1, chunks (tid&1)*4 .. +3
    int srow = tid >> 1;
    int sc4 = (tid & 1) * 4;
    const unsigned char* mrowp = g_mask8 + ((size_t)(b * LL + l0 + srow)) * LL + sc4 * 8;
    const __half* up = g_ut + ((size_t)(b * DD + d0 + srow)) * LL + sc4 * 8;

    uint32_t ast = sb + SMB_A + SA(srow, sc4);  // base of this thread's 4 A chunks (consecutive swizzle offsets computed per-j)

    // ---- prologue ----
    uint2 areg[4];
#pragma unroll
    for (int j = 0; j < 4; j++) areg[j] = *(const uint2*)(mrowp + 0 + j * 8);  // A(0)
    // cp.async B0 -> buf0 (group 0)
#pragma unroll
    for (int j = 0; j < 4; j++)
        CPASYNC16(sb + SMB_B0 + SA(srow, sc4 + j), (const void*)(up + 0 + j * 8));
    CPCOMMIT();
    // cp.async B1 -> buf1 (group 1)
#pragma unroll
    for (int j = 0; j < 4; j++)
        CPASYNC16(sb + SMB_B0 + 16384u + SA(srow, sc4 + j), (const void*)(up + 64 + j * 8));
    CPCOMMIT();
    // STS A(0)
#pragma unroll
    for (int j = 0; j < 4; j++) {
        uint32_t r0 = m2f16(areg[j].x), r1 = m2f16(areg[j].x >> 16);
        uint32_t r2 = m2f16(areg[j].y), r3 = m2f16(areg[j].y >> 16);
        STS128V(sb + SMB_A + SA(srow, sc4 + j), r0, r1, r2, r3);
    }
    // LDG A(1)
#pragma unroll
    for (int j = 0; j < 4; j++) areg[j] = *(const uint2*)(mrowp + 64 + j * 8);
    CPWAIT1();       // B(0) ready
    __syncthreads(); // A(0) visible

    for (int kt = 0; kt < 32; ++kt) {
        uint32_t bbase = sb + SMB_B0 + (uint32_t)(kt & 1) * 16384u;
        // ---- compute chunk kt ----
#pragma unroll
        for (int ki = 0; ki < 4; ki++) {
            uint32_t af[2][4];
#pragma unroll
            for (int mi = 0; mi < 2; mi++)
                ldsm4(af[mi], sb + SMB_A + SA(rA0 + mi * 16, ki * 2 + chA));
#pragma unroll
            for (int p = 0; p < 4; p++) {
                uint32_t bf[4];
                ldsm4(bf, bbase + SA(rB0 + p * 16, ki * 2 + chB));
#pragma unroll
                for (int mi = 0; mi < 2; mi++) {
                    mma_f16(acc[mi][2 * p], af[mi], bf);
                    mma_f16(acc[mi][2 * p + 1], af[mi], bf + 2);
                }
            }
        }
        if (kt == 31) break;
        __syncthreads();  // done reading A(kt) and B buffers
        // ---- stage A(kt+1) from regs ----
#pragma unroll
        for (int j = 0; j < 4; j++) {
            uint32_t r0 = m2f16(areg[j].x), r1 = m2f16(areg[j].x >> 16);
            uint32_t r2 = m2f16(areg[j].y), r3 = m2f16(areg[j].y >> 16);
            STS128V(sb + SMB_A + SA(srow, sc4 + j), r0, r1, r2, r3);
        }
        // ---- LDG A(kt+2) ----
        if (kt < 30) {
            int s0n = (kt + 2) * 64;
#pragma unroll
            for (int j = 0; j < 4; j++) areg[j] = *(const uint2*)(mrowp + s0n + j * 8);
        }
        // ---- cp.async B(kt+2) into buffer just freed ----
        if (kt < 30) {
            int s0n = (kt + 2) * 64;
            uint32_t nb = sb + SMB_B0 + (uint32_t)(kt & 1) * 16384u;
#pragma unroll
            for (int j = 0; j < 4; j++)
                CPASYNC16(nb + SA(srow, sc4 + j), (const void*)(up + s0n + j * 8));
        }
        CPCOMMIT();      // always commit to keep group counting stable
        CPWAIT1();       // B(kt+1) ready (only B(kt+2) may remain in flight)
        __syncthreads(); // A(kt+1) visible + B buffer handoff
    }

    // epilogue: scale rows by zinv, store fp32
    int g = lane >> 2, tg = lane & 3;
#pragma unroll
    for (int mi = 0; mi < 2; mi++) {
#pragma unroll
        for (int h = 0; h < 2; h++) {
            int row = warpM * 32 + mi * 16 + h * 8 + g;
            float zi = g_zinv[b * LL + l0 + row];
            float* orow = out + ((size_t)(b * LL + l0 + row)) * DD + d0 + warpN * 64;
#pragma unroll
            for (int ni = 0; ni < 8; ni++) {
                float2 val;
                val.x = acc[mi][ni][h * 2] * zi;
                val.y = acc[mi][ni][h * 2 + 1] * zi;
                *(float2*)(orow + ni * 8 + tg * 2) = val;
            }
        }
    }
}

// ---------------- launch ----------------
extern "C" void kernel_launch(void* const* d_in, const int* in_sizes, int n_in,
                              void* d_out, int out_size) {
    (void)in_sizes; (void)n_in; (void)out_size;
    // inputs: 0=q, 1=k, 2=v, 3=attn_mask, 4=W1, 5=b1, 6=W2, 7=b2
    const float* k = (const float*)d_in[1];
    const float* v = (const float*)d_in[2];
    const void* mask = d_in[3];
    const float* W2 = (const float*)d_in[6];
    const float* b2 = (const float*)d_in[7];

    float* out = (float*)d_out;                // [B, L, D]
    float* attn = out + (size_t)BB * LL * DD;  // [B, L, L]

    detect_kernel<<<1, 1024>>>((const unsigned int*)mask);
    repack_kernel<<<(int)(((size_t)BB * LL * LL) / 4096), 256>>>(mask);
    ks_kernel<<<BB * LL / 8, 256>>>(k, W2, b2);
    maxexp_kernel<<<BB, 256>>>();
    ut_kernel<<<dim3(DD / 32, LL / 32, BB), 256>>>(v);
    zattn_kernel<<<BB * LL / 8, 256>>>(attn);
    gemm_kernel<<<dim3(DD / 128, LL / 128, BB), 256>>>(out);
}

// round 7
// speedup vs baseline: 2.1311x; 1.0723x over previous
#include <cuda_runtime.h>
#include <cuda_bf16.h>
#include <cuda_fp16.h>
#include <cstdint>
#include <cstddef>

#define BB 8
#define LL 2048
#define DD 1024

// ---------------- scratch (device globals; allocation-free) ----------------
__device__ float g_ks[BB * LL];
__device__ float g_e[BB * LL];
__device__ float g_zinv[BB * LL];
__device__ int g_is32;
__device__ unsigned char g_mask8[(size_t)BB * LL * LL];  // 0/1 bytes
__device__ __half g_ut[(size_t)BB * DD * LL];            // U^T fp16: [b][d][s]

// ---------------- helpers ----------------
static __device__ __forceinline__ uint32_t smem_u32(const void* p) {
    uint32_t a;
    asm("{ .reg .u64 t; cvta.to.shared.u64 t, %1; cvt.u32.u64 %0, t; }" : "=r"(a) : "l"(p));
    return a;
}

#define STS128V(a, r0, r1, r2, r3) \
    asm volatile("st.shared.v4.b32 [%0], {%1, %2, %3, %4};" :: "r"(a), "r"(r0), "r"(r1), "r"(r2), "r"(r3) : "memory")

#define CPASYNC16(dst, src) \
    asm volatile("cp.async.cg.shared.global [%0], [%1], 16;" :: "r"(dst), "l"(src) : "memory")
#define CPCOMMIT() asm volatile("cp.async.commit_group;" ::: "memory")
#define CPWAIT1() asm volatile("cp.async.wait_group 1;" ::: "memory")

static __device__ __forceinline__ void ldsm4(uint32_t* r, uint32_t addr) {
    asm volatile("ldmatrix.sync.aligned.m8n8.x4.shared.b16 {%0,%1,%2,%3}, [%4];"
                 : "=r"(r[0]), "=r"(r[1]), "=r"(r[2]), "=r"(r[3]) : "r"(addr));
}

static __device__ __forceinline__ void mma_f16(float* c, const uint32_t* a, const uint32_t* b) {
    asm volatile(
        "mma.sync.aligned.m16n8k16.row.col.f32.f16.f16.f32 "
        "{%0,%1,%2,%3}, {%4,%5,%6,%7}, {%8,%9}, {%0,%1,%2,%3};"
        : "+f"(c[0]), "+f"(c[1]), "+f"(c[2]), "+f"(c[3])
        : "r"(a[0]), "r"(a[1]), "r"(a[2]), "r"(a[3]), "r"(b[0]), "r"(b[1]));
}

// swizzled SMEM offset: tiles are 128 rows x 64 fp16 (128B rows, 8 x 16B chunks)
#define SA(row, chunk) ((uint32_t)((row) * 128 + ((((uint32_t)(chunk)) ^ ((uint32_t)(row) & 7u)) << 4)))

// 2 mask bytes -> fp16x2 (1.0 where NOT masked, 0.0 where masked)
static __device__ __forceinline__ uint32_t m2f16(uint32_t w) {
    uint32_t lo = (w & 0x000000FFu) ? 0u : 0x3C00u;
    uint32_t hi = (w & 0x0000FF00u) ? 0u : 0x3C00u;
    return lo | (hi << 16);
}

// ---------------- Pass 0a: detect mask dtype (int32 vs uint8) ----------------
__global__ void detect_kernel(const unsigned int* m) {
    __shared__ int s;
    if (threadIdx.x == 0) s = 0;
    __syncthreads();
    if (m[threadIdx.x] & 0xFFFFFF00u) atomicOr(&s, 1);
    __syncthreads();
    if (threadIdx.x == 0) g_is32 = s ? 0 : 1;
}

// ---------------- Pass 0b: repack mask to normalized bytes ----------------
__global__ __launch_bounds__(256) void repack_kernel(const void* maskp) {
    size_t base = ((size_t)blockIdx.x * 256 + threadIdx.x) * 16;
    uint4 ov;
    if (g_is32) {
        const uint4* mi = (const uint4*)((const int*)maskp + base);
        unsigned char ob[16];
#pragma unroll
        for (int j = 0; j < 4; j++) {
            uint4 w = mi[j];
            ob[j * 4 + 0] = w.x ? 1 : 0;
            ob[j * 4 + 1] = w.y ? 1 : 0;
            ob[j * 4 + 2] = w.z ? 1 : 0;
            ob[j * 4 + 3] = w.w ? 1 : 0;
        }
        ov = *(const uint4*)ob;
    } else {
        ov = *(const uint4*)((const unsigned char*)maskp + base);
    }
    *(uint4*)(g_mask8 + base) = ov;
}

// ---------------- Pass 1: k_s[b,s] = k . W2 + b2 ----------------
__global__ __launch_bounds__(256) void ks_kernel(const float* __restrict__ k,
                                                 const float* __restrict__ W2,
                                                 const float* __restrict__ b2) {
    int w = threadIdx.x >> 5, lane = threadIdx.x & 31;
    int r = blockIdx.x * 8 + w;
    const float4* kr = (const float4*)(k + (size_t)r * DD);
    const float4* w4 = (const float4*)W2;
    float s = 0.f;
#pragma unroll
    for (int i = 0; i < 8; i++) {
        float4 a = kr[lane + 32 * i];
        float4 b = w4[lane + 32 * i];
        s += a.x * b.x + a.y * b.y + a.z * b.z + a.w * b.w;
    }
#pragma unroll
    for (int o = 16; o; o >>= 1) s += __shfl_xor_sync(0xFFFFFFFFu, s, o);
    if (lane == 0) g_ks[r] = s + b2[0];
}

// ---------------- Pass 2: per-b max and e = exp(ks - max) ----------------
__global__ __launch_bounds__(256) void maxexp_kernel() {
    int b = blockIdx.x;
    __shared__ float red[256];
    float m = -1e30f;
    for (int i = threadIdx.x; i < LL; i += 256) m = fmaxf(m, g_ks[b * LL + i]);
    red[threadIdx.x] = m;
    __syncthreads();
    for (int s = 128; s; s >>= 1) {
        if (threadIdx.x < s) red[threadIdx.x] = fmaxf(red[threadIdx.x], red[threadIdx.x + s]);
        __syncthreads();
    }
    float M = red[0];
    for (int i = threadIdx.x; i < LL; i += 256) g_e[b * LL + i] = expf(g_ks[b * LL + i] - M);
}

// ---------------- Pass 3: U^T fp16 build (U = e * v, transposed to [b][d][s]) ----------------
__global__ __launch_bounds__(256) void ut_kernel(const float* __restrict__ v) {
    __shared__ float tile[32][33];
    int b = blockIdx.z;
    int s0 = blockIdx.y * 32, d0 = blockIdx.x * 32;
    int r = threadIdx.x >> 5, c = threadIdx.x & 31;
#pragma unroll
    for (int i = 0; i < 4; i++) {
        int sl = r + i * 8;
        tile[sl][c] = g_e[b * LL + s0 + sl] * v[((size_t)b * LL + s0 + sl) * DD + d0 + c];
    }
    __syncthreads();
#pragma unroll
    for (int i = 0; i < 4; i++) {
        int dl = r + i * 8;
        float u = tile[c][dl];
        g_ut[((size_t)b * DD + d0 + dl) * LL + s0 + c] = __float2half(u);
    }
}

// ---------------- Pass 4: Z[b,l], zinv, attn output ----------------
__global__ __launch_bounds__(256) void zattn_kernel(float* __restrict__ attn) {
    __shared__ __align__(16) float se[LL];
    int b = blockIdx.x >> 8;
    int l0 = (blockIdx.x & 255) * 8;
    for (int i = threadIdx.x; i < LL; i += 256) se[i] = g_e[b * LL + i];
    __syncthreads();
    int w = threadIdx.x >> 5, lane = threadIdx.x & 31;
    int l = l0 + w;
    const uint32_t* mrow = (const uint32_t*)(g_mask8 + ((size_t)b * LL + l) * LL);
    const float4* e4 = (const float4*)se;
    uint32_t mw[16];
    float z = 0.f;
#pragma unroll
    for (int i = 0; i < 16; i++) {
        uint32_t m = mrow[lane + 32 * i];
        mw[i] = m;
        float4 ev = e4[lane + 32 * i];
        if (!(m & 0x000000FFu)) z += ev.x;
        if (!(m & 0x0000FF00u)) z += ev.y;
        if (!(m & 0x00FF0000u)) z += ev.z;
        if (!(m & 0xFF000000u)) z += ev.w;
    }
#pragma unroll
    for (int o = 16; o; o >>= 1) z += __shfl_xor_sync(0xFFFFFFFFu, z, o);
    float zi = 1.f / z;
    if (lane == 0) g_zinv[b * LL + l] = zi;
    float4* arow = (float4*)(attn + ((size_t)b * LL + l) * LL);
#pragma unroll
    for (int i = 0; i < 16; i++) {
        uint32_t m = mw[i];
        float4 ev = e4[lane + 32 * i];
        float4 o4;
        o4.x = (m & 0x000000FFu) ? 0.f : ev.x * zi;
        o4.y = (m & 0x0000FF00u) ? 0.f : ev.y * zi;
        o4.z = (m & 0x00FF0000u) ? 0.f : ev.z * zi;
        o4.w = (m & 0xFF000000u) ? 0.f : ev.w * zi;
        arow[lane + 32 * i] = o4;
    }
}

// ================= Pass 5 (preferred): 3-stage pipelined fp16 GEMM, 96KB dyn SMEM =================
// CTA tile 128(l) x 128(d), K-chunk 64(s), stages s%3: [A 16KB | B 16KB] per stage.
// One __syncthreads per chunk; A via LDG->cvt->STS 2 ahead; B via cp.async 2 ahead.
__global__ __launch_bounds__(256, 2) void gemm_kernel96(float* __restrict__ out) {
    extern __shared__ __align__(128) unsigned char dsm[];
    uint32_t sb = smem_u32(dsm);
    int tid = threadIdx.x, wid = tid >> 5, lane = tid & 31;
    int b = blockIdx.z, l0 = blockIdx.y * 128, d0 = blockIdx.x * 128;
    int warpM = wid & 3, warpN = wid >> 2;

    float acc[2][8][4];
#pragma unroll
    for (int i = 0; i < 2; i++)
#pragma unroll
        for (int j = 0; j < 8; j++)
#pragma unroll
            for (int q = 0; q < 4; q++) acc[i][j][q] = 0.f;

    int sub = lane >> 3, l7 = lane & 7;
    int rA0 = warpM * 32 + (sub & 1) * 8 + l7;
    int chA = (sub >> 1);
    int rB0 = warpN * 64 + (sub >> 1) * 8 + l7;
    int chB = (sub & 1);

    int srow = tid >> 1;
    int sc4 = (tid & 1) * 4;
    const unsigned char* mrowp = g_mask8 + ((size_t)(b * LL + l0 + srow)) * LL + sc4 * 8;
    const __half* up = g_ut + ((size_t)(b * DD + d0 + srow)) * LL + sc4 * 8;

    // ---- prologue: stages 0 and 1 ----
    uint2 areg[4];
#pragma unroll
    for (int st = 0; st < 2; st++) {
        uint32_t ab = sb + (uint32_t)st * 32768u;
#pragma unroll
        for (int j = 0; j < 4; j++) areg[j] = *(const uint2*)(mrowp + st * 64 + j * 8);
#pragma unroll
        for (int j = 0; j < 4; j++) {
            uint32_t r0 = m2f16(areg[j].x), r1 = m2f16(areg[j].x >> 16);
            uint32_t r2 = m2f16(areg[j].y), r3 = m2f16(areg[j].y >> 16);
            STS128V(ab + SA(srow, sc4 + j), r0, r1, r2, r3);
        }
#pragma unroll
        for (int j = 0; j < 4; j++)
            CPASYNC16(ab + 16384u + SA(srow, sc4 + j), (const void*)(up + st * 64 + j * 8));
        CPCOMMIT();
    }

    int st = 0;  // kt % 3
    for (int kt = 0; kt < 32; ++kt) {
        CPWAIT1();       // B(kt) arrived
        __syncthreads(); // stage kt fully staged; stage (kt+2)%3 free (readers of kt-1 done)

        // early LDG for A(kt+2)
        if (kt < 30) {
            int s0n = (kt + 2) * 64;
#pragma unroll
            for (int j = 0; j < 4; j++) areg[j] = *(const uint2*)(mrowp + s0n + j * 8);
        }

        // ---- compute chunk kt from stage st ----
        uint32_t abase = sb + (uint32_t)st * 32768u;
        uint32_t bbase = abase + 16384u;
#pragma unroll
        for (int ki = 0; ki < 4; ki++) {
            uint32_t af[2][4];
#pragma unroll
            for (int mi = 0; mi < 2; mi++)
                ldsm4(af[mi], abase + SA(rA0 + mi * 16, ki * 2 + chA));
#pragma unroll
            for (int p = 0; p < 4; p++) {
                uint32_t bf[4];
                ldsm4(bf, bbase + SA(rB0 + p * 16, ki * 2 + chB));
#pragma unroll
                for (int mi = 0; mi < 2; mi++) {
                    mma_f16(acc[mi][2 * p], af[mi], bf);
                    mma_f16(acc[mi][2 * p + 1], af[mi], bf + 2);
                }
            }
        }

        // ---- stage (kt+2) into the freed buffer ----
        if (kt < 30) {
            int s0n = (kt + 2) * 64;
            int stn = st + 2; if (stn >= 3) stn -= 3;
            uint32_t nb = sb + (uint32_t)stn * 32768u;
#pragma unroll
            for (int j = 0; j < 4; j++) {
                uint32_t r0 = m2f16(areg[j].x), r1 = m2f16(areg[j].x >> 16);
                uint32_t r2 = m2f16(areg[j].y), r3 = m2f16(areg[j].y >> 16);
                STS128V(nb + SA(srow, sc4 + j), r0, r1, r2, r3);
            }
#pragma unroll
            for (int j = 0; j < 4; j++)
                CPASYNC16(nb + 16384u + SA(srow, sc4 + j), (const void*)(up + s0n + j * 8));
        }
        CPCOMMIT();  // keep group counting stable even in tail
        if (++st == 3) st = 0;
    }

    // epilogue
    int g = lane >> 2, tg = lane & 3;
#pragma unroll
    for (int mi = 0; mi < 2; mi++) {
#pragma unroll
        for (int h = 0; h < 2; h++) {
            int row = warpM * 32 + mi * 16 + h * 8 + g;
            float zi = g_zinv[b * LL + l0 + row];
            float* orow = out + ((size_t)(b * LL + l0 + row)) * DD + d0 + warpN * 64;
#pragma unroll
            for (int ni = 0; ni < 8; ni++) {
                float2 val;
                val.x = acc[mi][ni][h * 2] * zi;
                val.y = acc[mi][ni][h * 2 + 1] * zi;
                *(float2*)(orow + ni * 8 + tg * 2) = val;
            }
        }
    }
}

// ================= Pass 5 (fallback): R6 48KB static version =================
#define SMB_A  0u
#define SMB_B0 16384u

__global__ __launch_bounds__(256, 2) void gemm_kernel48(float* __restrict__ out) {
    __shared__ __align__(128) unsigned char smem[49152];
    uint32_t sb = smem_u32(smem);
    int tid = threadIdx.x, wid = tid >> 5, lane = tid & 31;
    int b = blockIdx.z, l0 = blockIdx.y * 128, d0 = blockIdx.x * 128;
    int warpM = wid & 3, warpN = wid >> 2;

    float acc[2][8][4];
#pragma unroll
    for (int i = 0; i < 2; i++)
#pragma unroll
        for (int j = 0; j < 8; j++)
#pragma unroll
            for (int q = 0; q < 4; q++) acc[i][j][q] = 0.f;

    int sub = lane >> 3, l7 = lane & 7;
    int rA0 = warpM * 32 + (sub & 1) * 8 + l7;
    int chA = (sub >> 1);
    int rB0 = warpN * 64 + (sub >> 1) * 8 + l7;
    int chB = (sub & 1);

    int srow = tid >> 1;
    int sc4 = (tid & 1) * 4;
    const unsigned char* mrowp = g_mask8 + ((size_t)(b * LL + l0 + srow)) * LL + sc4 * 8;
    const __half* up = g_ut + ((size_t)(b * DD + d0 + srow)) * LL + sc4 * 8;

    uint2 areg[4];
#pragma unroll
    for (int j = 0; j < 4; j++) areg[j] = *(const uint2*)(mrowp + 0 + j * 8);
#pragma unroll
    for (int j = 0; j < 4; j++)
        CPASYNC16(sb + SMB_B0 + SA(srow, sc4 + j), (const void*)(up + 0 + j * 8));
    CPCOMMIT();
#pragma unroll
    for (int j = 0; j < 4; j++)
        CPASYNC16(sb + SMB_B0 + 16384u + SA(srow, sc4 + j), (const void*)(up + 64 + j * 8));
    CPCOMMIT();
#pragma unroll
    for (int j = 0; j < 4; j++) {
        uint32_t r0 = m2f16(areg[j].x), r1 = m2f16(areg[j].x >> 16);
        uint32_t r2 = m2f16(areg[j].y), r3 = m2f16(areg[j].y >> 16);
        STS128V(sb + SMB_A + SA(srow, sc4 + j), r0, r1, r2, r3);
    }
#pragma unroll
    for (int j = 0; j < 4; j++) areg[j] = *(const uint2*)(mrowp + 64 + j * 8);
    CPWAIT1();
    __syncthreads();

    for (int kt = 0; kt < 32; ++kt) {
        uint32_t bbase = sb + SMB_B0 + (uint32_t)(kt & 1) * 16384u;
#pragma unroll
        for (int ki = 0; ki < 4; ki++) {
            uint32_t af[2][4];
#pragma unroll
            for (int mi = 0; mi < 2; mi++)
                ldsm4(af[mi], sb + SMB_A + SA(rA0 + mi * 16, ki * 2 + chA));
#pragma unroll
            for (int p = 0; p < 4; p++) {
                uint32_t bf[4];
                ldsm4(bf, bbase + SA(rB0 + p * 16, ki * 2 + chB));
#pragma unroll
                for (int mi = 0; mi < 2; mi++) {
                    mma_f16(acc[mi][2 * p], af[mi], bf);
                    mma_f16(acc[mi][2 * p + 1], af[mi], bf + 2);
                }
            }
        }
        if (kt == 31) break;
        __syncthreads();
#pragma unroll
        for (int j = 0; j < 4; j++) {
            uint32_t r0 = m2f16(areg[j].x), r1 = m2f16(areg[j].x >> 16);
            uint32_t r2 = m2f16(areg[j].y), r3 = m2f16(areg[j].y >> 16);
            STS128V(sb + SMB_A + SA(srow, sc4 + j), r0, r1, r2, r3);
        }
        if (kt < 30) {
            int s0n = (kt + 2) * 64;
#pragma unroll
            for (int j = 0; j < 4; j++) areg[j] = *(const uint2*)(mrowp + s0n + j * 8);
#pragma unroll
            for (int j = 0; j < 4; j++)
                CPASYNC16(sb + SMB_B0 + (uint32_t)(kt & 1) * 16384u + SA(srow, sc4 + j),
                          (const void*)(up + s0n + j * 8));
        }
        CPCOMMIT();
        CPWAIT1();
        __syncthreads();
    }

    int g = lane >> 2, tg = lane & 3;
#pragma unroll
    for (int mi = 0; mi < 2; mi++) {
#pragma unroll
        for (int h = 0; h < 2; h++) {
            int row = warpM * 32 + mi * 16 + h * 8 + g;
            float zi = g_zinv[b * LL + l0 + row];
            float* orow = out + ((size_t)(b * LL + l0 + row)) * DD + d0 + warpN * 64;
#pragma unroll
            for (int ni = 0; ni < 8; ni++) {
                float2 val;
                val.x = acc[mi][ni][h * 2] * zi;
                val.y = acc[mi][ni][h * 2 + 1] * zi;
                *(float2*)(orow + ni * 8 + tg * 2) = val;
            }
        }
    }
}

// ---------------- launch ----------------
extern "C" void kernel_launch(void* const* d_in, const int* in_sizes, int n_in,
                              void* d_out, int out_size) {
    (void)in_sizes; (void)n_in; (void)out_size;
    const float* k = (const float*)d_in[1];
    const float* v = (const float*)d_in[2];
    const void* mask = d_in[3];
    const float* W2 = (const float*)d_in[6];
    const float* b2 = (const float*)d_in[7];

    float* out = (float*)d_out;                // [B, L, D]
    float* attn = out + (size_t)BB * LL * DD;  // [B, L, L]

    detect_kernel<<<1, 1024>>>((const unsigned int*)mask);
    repack_kernel<<<(int)(((size_t)BB * LL * LL) / 4096), 256>>>(mask);
    ks_kernel<<<BB * LL / 8, 256>>>(k, W2, b2);
    maxexp_kernel<<<BB, 256>>>();
    ut_kernel<<<dim3(DD / 32, LL / 32, BB), 256>>>(v);
    zattn_kernel<<<BB * LL / 8, 256>>>(attn);

    dim3 grid(DD / 128, LL / 128, BB);
    cudaError_t e = cudaFuncSetAttribute(gemm_kernel96,
                                         cudaFuncAttributeMaxDynamicSharedMemorySize, 98304);
    if (e == cudaSuccess) {
        gemm_kernel96<<<grid, 256, 98304>>>(out);
    } else {
        (void)cudaGetLastError();  // clear sticky error from failed attribute set
        gemm_kernel48<<<grid, 256>>>(out);
    }
}